// round 5
// baseline (speedup 1.0000x reference)
#include <cuda_runtime.h>
#include <cstdint>

#define DIMM   1024
#define NHEADS 16
#define HD     64
#define BATCH  2
#define SEQ    2048
#define MROWS  (BATCH*SEQ)   /* 4096 */
#define WFLOATS (DIMM*DIMM)  /* 1048576 */

// Scratch (allocation-free)
__device__ float g_q[MROWS*DIMM];
__device__ float g_k[MROWS*DIMM];
__device__ float g_v[MROWS*DIMM];
__device__ float g_att[MROWS*DIMM];
__device__ float g_xr[MROWS*DIMM];
__device__ float g_wr[4*WFLOATS];

// ===========================================================================
// Helpers
// ===========================================================================
__device__ __forceinline__ uint32_t smem_u32(const void* p) {
    uint32_t a;
    asm("{ .reg .u64 t; cvta.to.shared.u64 t, %1; cvt.u32.u64 %0, t; }" : "=r"(a) : "l"(p));
    return a;
}
__device__ __forceinline__ void cp_async16(uint32_t dst, const void* src) {
    asm volatile("cp.async.cg.shared.global [%0], [%1], 16;" :: "r"(dst), "l"(src) : "memory");
}
#define CP_COMMIT()  asm volatile("cp.async.commit_group;" ::: "memory")
#define CP_WAIT(n)   asm volatile("cp.async.wait_group %0;" :: "n"(n) : "memory")

__device__ __forceinline__ uint32_t f2tf(float f) {
    uint32_t r;
    asm("cvt.rna.tf32.f32 %0, %1;" : "=r"(r) : "f"(f));
    return r;
}
// D += A * B  (m16n8k8, tf32)
__device__ __forceinline__ void mma8(float* c, const uint32_t* a, const uint32_t* b) {
    asm volatile(
        "mma.sync.aligned.m16n8k8.row.col.f32.tf32.tf32.f32 "
        "{%0,%1,%2,%3}, {%4,%5,%6,%7}, {%8,%9}, {%0,%1,%2,%3};"
        : "+f"(c[0]), "+f"(c[1]), "+f"(c[2]), "+f"(c[3])
        : "r"(a[0]), "r"(a[1]), "r"(a[2]), "r"(a[3]), "r"(b[0]), "r"(b[1]));
}

// FMA-pipe exp: e^(s * 0.125). Clamps low (masked entries -> ~2^-100 ~= 0).
__device__ __forceinline__ float fexp_s(float s) {
    float y = s * 0.18033688011112042f;      // 0.125 * log2(e)
    y = fmaxf(y, -100.0f);
    float t = __fadd_rn(y, 12582912.0f);     // rint(y) into mantissa
    float n = __fsub_rn(t, 12582912.0f);
    float f = __fsub_rn(y, n);
    int   e = __float_as_int(t) << 23;       // n << 23
    float p = 1.3333558146e-3f;
    p = fmaf(p, f, 9.618129107e-3f);
    p = fmaf(p, f, 5.550410866e-2f);
    p = fmaf(p, f, 2.402265069e-1f);
    p = fmaf(p, f, 6.931471806e-1f);
    p = fmaf(p, f, 1.0f);
    return __int_as_float(__float_as_int(p) + e);
}

// ===========================================================================
// Elementwise tf32 rounding pass
// ===========================================================================
__global__ __launch_bounds__(256) void round_k(const float* __restrict__ in,
                                               float* __restrict__ out, int n4)
{
    int i = blockIdx.x * blockDim.x + threadIdx.x;
    if (i < n4) {
        float4 v = ((const float4*)in)[i];
        v.x = __uint_as_float(f2tf(v.x));
        v.y = __uint_as_float(f2tf(v.y));
        v.z = __uint_as_float(f2tf(v.z));
        v.w = __uint_as_float(f2tf(v.w));
        ((float4*)out)[i] = v;
    }
}

// ===========================================================================
// tf32 mma.sync GEMM (unchanged from R4)
// ===========================================================================
#define BK    32
#define GST   2
#define APAD  36
#define GSTAGE_U32 (2*128*APAD)
#define GSMEM_BYTES (GST * GSTAGE_U32 * 4)   /* 73728 */
#define KT    (DIMM / BK)

template<bool ROUND>
__global__ __launch_bounds__(256, 2) void gemm_mma(
    const float* __restrict__ A,
    const float* __restrict__ B0, const float* __restrict__ B1, const float* __restrict__ B2,
    float* __restrict__ C0, float* __restrict__ C1, float* __restrict__ C2)
{
    extern __shared__ uint32_t sm[];
    const int tid  = threadIdx.x;
    const int wid  = tid >> 5;
    const int lane = tid & 31;
    const int wm   = wid >> 2;
    const int wn   = wid & 3;
    const int r0   = lane >> 2;
    const int q4   = lane & 3;

    const float* Bz = (blockIdx.z == 0) ? B0 : (blockIdx.z == 1) ? B1 : B2;
    float*       Cz = (blockIdx.z == 0) ? C0 : (blockIdx.z == 1) ? C1 : C2;

    const float* Ag = A  + (size_t)(blockIdx.y * 128) * DIMM;
    const float* Bg = Bz + (size_t)(blockIdx.x * 128) * DIMM;
    const uint32_t sbase = smem_u32(sm);

    auto load_tile = [&](int kt, int s) {
        uint32_t ab = sbase + s * GSTAGE_U32 * 4;
        uint32_t bb = ab + 128 * APAD * 4;
#pragma unroll
        for (int i = 0; i < 4; i++) {
            int idx = i * 256 + tid;
            int row = idx >> 3, seg = idx & 7;
            cp_async16(ab + (row * APAD + seg * 4) * 4,
                       Ag + (size_t)row * DIMM + kt * BK + seg * 4);
        }
#pragma unroll
        for (int i = 0; i < 4; i++) {
            int idx = i * 256 + tid;
            int row = idx >> 3, seg = idx & 7;
            cp_async16(bb + (row * APAD + seg * 4) * 4,
                       Bg + (size_t)row * DIMM + kt * BK + seg * 4);
        }
        CP_COMMIT();
    };

    float c[4][4][4];
#pragma unroll
    for (int i = 0; i < 4; i++)
#pragma unroll
        for (int j = 0; j < 4; j++)
#pragma unroll
            for (int u = 0; u < 4; u++) c[i][j][u] = 0.f;

    load_tile(0, 0);
    load_tile(1, 1);

    for (int kt = 0; kt < KT; kt++) {
        if (kt + 1 < KT) { CP_WAIT(1); } else { CP_WAIT(0); }
        __syncthreads();
        const uint32_t* Asw = sm + (kt & 1) * GSTAGE_U32;
        const uint32_t* Bsw = Asw + 128 * APAD;

#pragma unroll
        for (int kk = 0; kk < BK / 8; kk++) {
            const int k = kk * 8 + q4;
            uint32_t a[4][4], b[4][2];
#pragma unroll
            for (int i = 0; i < 4; i++) {
                int r = wm * 64 + i * 16 + r0;
                a[i][0] = Asw[r * APAD + k];
                a[i][1] = Asw[(r + 8) * APAD + k];
                a[i][2] = Asw[r * APAD + k + 4];
                a[i][3] = Asw[(r + 8) * APAD + k + 4];
            }
#pragma unroll
            for (int j = 0; j < 4; j++) {
                int n = wn * 32 + j * 8 + r0;
                b[j][0] = Bsw[n * APAD + k];
                b[j][1] = Bsw[n * APAD + k + 4];
            }
#pragma unroll
            for (int i = 0; i < 4; i++)
#pragma unroll
                for (int j = 0; j < 4; j++)
                    mma8(c[i][j], a[i], b[j]);
        }
        __syncthreads();
        if (kt + 2 < KT) load_tile(kt + 2, kt & 1);
    }

    float* Cg = Cz + (size_t)(blockIdx.y * 128 + wm * 64) * DIMM + blockIdx.x * 128 + wn * 32;
#pragma unroll
    for (int i = 0; i < 4; i++)
#pragma unroll
        for (int j = 0; j < 4; j++) {
            int lr = i * 16 + r0;
            int col = j * 8 + 2 * q4;
            if (ROUND) {
                float2 v0 = make_float2(__uint_as_float(f2tf(c[i][j][0])), __uint_as_float(f2tf(c[i][j][1])));
                float2 v1 = make_float2(__uint_as_float(f2tf(c[i][j][2])), __uint_as_float(f2tf(c[i][j][3])));
                *(float2*)(Cg + (size_t)lr * DIMM + col)       = v0;
                *(float2*)(Cg + (size_t)(lr + 8) * DIMM + col) = v1;
            } else {
                *(float2*)(Cg + (size_t)lr * DIMM + col)       = make_float2(c[i][j][0], c[i][j][1]);
                *(float2*)(Cg + (size_t)(lr + 8) * DIMM + col) = make_float2(c[i][j][2], c[i][j][3]);
            }
        }
}

// ===========================================================================
// Fused causal flash attention, tf32 mma.sync.
// 256 threads, 128 q-rows/CTA (8 warps x 16 rows), Q fragments hoisted to
// registers, cp.async double-buffered K/V, reversed qb order.
// ===========================================================================
#define QP 68
#define VP 72
#define FW_Q  0
#define FW_P  (128*QP)
#define FW_K  (2*128*QP)
#define FW_V  (FW_K + 2*64*QP)
#define FSMEM_WORDS (FW_V + 2*64*VP)
#define FSMEM_BYTES (FSMEM_WORDS * 4)   /* 141312 */

__global__ __launch_bounds__(256) void flash_tc(
    const float* __restrict__ gq, const float* __restrict__ gk,
    const float* __restrict__ gv, float* __restrict__ go)
{
    extern __shared__ uint32_t fsm[];
    uint32_t* Qs = fsm + FW_Q;
    uint32_t* Ps = fsm + FW_P;

    const int qb  = gridDim.x - 1 - blockIdx.x;   // heavy CTAs first
    const int bh  = blockIdx.y;
    const int b   = bh >> 4;
    const int h   = bh & 15;
    const int tid = threadIdx.x;
    const int wid = tid >> 5;          // 0..7
    const int lane = tid & 31;
    const int r0 = lane >> 2;
    const int q4 = lane & 3;
    const size_t base = (size_t)b * SEQ * DIMM + (size_t)h * HD;
    const uint32_t sbase = smem_u32(fsm);

    auto load_kv = [&](int t) {
        const int s = t & 1;
        const uint32_t kb = sbase + (FW_K + s * 64 * QP) * 4;
        const uint32_t vb = sbase + (FW_V + s * 64 * VP) * 4;
#pragma unroll
        for (int u = 0; u < 4; u++) {
            int idx = u * 256 + tid;           // 0..1023
            int r = idx >> 4, c4 = idx & 15;
            cp_async16(kb + (r * QP + c4 * 4) * 4,
                       gk + base + (size_t)(t * 64 + r) * DIMM + c4 * 4);
            cp_async16(vb + (r * VP + c4 * 4) * 4,
                       gv + base + (size_t)(t * 64 + r) * DIMM + c4 * 4);
        }
        CP_COMMIT();
    };

    // Q tile: 128 rows -> smem (pre-rounded tf32; raw copy)
#pragma unroll
    for (int u = 0; u < 8; u++) {
        int idx = u * 256 + tid;               // 0..2047
        int r = idx >> 4, c4 = idx & 15;
        float4 qv = *(const float4*)(gq + base + (size_t)(qb * 128 + r) * DIMM + c4 * 4);
        *(float4*)(Qs + r * QP + c4 * 4) = qv;
    }
    load_kv(0);
    __syncthreads();

    // Hoist Q fragments (invariant across KV tiles)
    const int arow = wid * 16 + r0;
    uint32_t qf[8][4];
#pragma unroll
    for (int ks = 0; ks < 8; ks++) {
        const int k = ks * 8 + q4;
        qf[ks][0] = Qs[arow * QP + k];
        qf[ks][1] = Qs[(arow + 8) * QP + k];
        qf[ks][2] = Qs[arow * QP + k + 4];
        qf[ks][3] = Qs[(arow + 8) * QP + k + 4];
    }

    float o[8][4];
#pragma unroll
    for (int j = 0; j < 8; j++)
#pragma unroll
        for (int u = 0; u < 4; u++) o[j][u] = 0.f;
    float l0 = 0.f, l1 = 0.f;

    const int nt = 2 * qb + 2;
    const int grow0 = qb * 128 + arow;
    const int grow1 = grow0 + 8;

    for (int t = 0; t < nt; t++) {
        if (t + 1 < nt) load_kv(t + 1);
        if (t + 1 < nt) { CP_WAIT(1); } else { CP_WAIT(0); }
        __syncthreads();

        const uint32_t* Ks = fsm + FW_K + (t & 1) * 64 * QP;
        const uint32_t* Vs = fsm + FW_V + (t & 1) * 64 * VP;

        // ---- S = Q @ K^T ----
        float c[8][4];
#pragma unroll
        for (int j = 0; j < 8; j++)
#pragma unroll
            for (int u = 0; u < 4; u++) c[j][u] = 0.f;

#pragma unroll
        for (int ks = 0; ks < 8; ks++) {
            const int k = ks * 8 + q4;
#pragma unroll
            for (int j = 0; j < 8; j++) {
                uint32_t bf[2];
                int n = j * 8 + r0;
                bf[0] = Ks[n * QP + k];
                bf[1] = Ks[n * QP + k + 4];
                mma8(c[j], qf[ks], bf);
            }
        }

        // ---- causal mask + exp (FMA pipe) + row sums ----
        const bool need0 = (t * 64 + 63) > grow0;
        const bool need1 = (t * 64 + 63) > grow1;
        float s0 = 0.f, s1 = 0.f;
#pragma unroll
        for (int j = 0; j < 8; j++) {
            int col = t * 64 + j * 8 + 2 * q4;
            if (need0) {
                if (col     > grow0) c[j][0] = -1e9f;
                if (col + 1 > grow0) c[j][1] = -1e9f;
            }
            if (need1) {
                if (col     > grow1) c[j][2] = -1e9f;
                if (col + 1 > grow1) c[j][3] = -1e9f;
            }
            c[j][0] = fexp_s(c[j][0]);
            c[j][1] = fexp_s(c[j][1]);
            c[j][2] = fexp_s(c[j][2]);
            c[j][3] = fexp_s(c[j][3]);
            s0 += c[j][0] + c[j][1];
            s1 += c[j][2] + c[j][3];
        }
        s0 += __shfl_xor_sync(0xffffffffu, s0, 1);
        s0 += __shfl_xor_sync(0xffffffffu, s0, 2);
        s1 += __shfl_xor_sync(0xffffffffu, s1, 1);
        s1 += __shfl_xor_sync(0xffffffffu, s1, 2);
        l0 += s0;
        l1 += s1;

        // ---- P -> smem (per-warp rows), then O += P @ V ----
        __syncwarp();
#pragma unroll
        for (int j = 0; j < 8; j++) {
            int pcol = j * 8 + 2 * q4;
            Ps[arow * QP + pcol]           = f2tf(c[j][0]);
            Ps[arow * QP + pcol + 1]       = f2tf(c[j][1]);
            Ps[(arow + 8) * QP + pcol]     = f2tf(c[j][2]);
            Ps[(arow + 8) * QP + pcol + 1] = f2tf(c[j][3]);
        }
        __syncwarp();

#pragma unroll
        for (int ks = 0; ks < 8; ks++) {
            const int k = ks * 8 + q4;
            uint32_t a[4];
            a[0] = Ps[arow * QP + k];
            a[1] = Ps[(arow + 8) * QP + k];
            a[2] = Ps[arow * QP + k + 4];
            a[3] = Ps[(arow + 8) * QP + k + 4];
#pragma unroll
            for (int j = 0; j < 8; j++) {
                uint32_t bf[2];
                int n = j * 8 + r0;
                bf[0] = Vs[(ks * 8 + q4) * VP + n];
                bf[1] = Vs[(ks * 8 + q4 + 4) * VP + n];
                mma8(o[j], a, bf);
            }
        }
        __syncthreads();   // buffer reuse safety
    }

    // ---- normalize + store (tf32-rounded for the out-proj GEMM) ----
    const float inv0 = 1.f / l0, inv1 = 1.f / l1;
    const int row0 = qb * 128 + arow;
#pragma unroll
    for (int j = 0; j < 8; j++) {
        int col = j * 8 + 2 * q4;
        float2 v0 = make_float2(__uint_as_float(f2tf(o[j][0] * inv0)),
                                __uint_as_float(f2tf(o[j][1] * inv0)));
        float2 v1 = make_float2(__uint_as_float(f2tf(o[j][2] * inv1)),
                                __uint_as_float(f2tf(o[j][3] * inv1)));
        *(float2*)(go + base + (size_t)row0 * DIMM + col)       = v0;
        *(float2*)(go + base + (size_t)(row0 + 8) * DIMM + col) = v1;
    }
}

// ===========================================================================
extern "C" void kernel_launch(void* const* d_in, const int* in_sizes, int n_in,
                              void* d_out, int out_size)
{
    (void)in_sizes; (void)n_in; (void)out_size;
    const float* x  = (const float*)d_in[0];
    const float* wq = (const float*)d_in[2];
    const float* wk = (const float*)d_in[3];
    const float* wv = (const float*)d_in[4];
    const float* wo = (const float*)d_in[5];
    float* out = (float*)d_out;

    float *q, *k, *v, *att, *xr, *wr;
    cudaGetSymbolAddress((void**)&q,   g_q);
    cudaGetSymbolAddress((void**)&k,   g_k);
    cudaGetSymbolAddress((void**)&v,   g_v);
    cudaGetSymbolAddress((void**)&att, g_att);
    cudaGetSymbolAddress((void**)&xr,  g_xr);
    cudaGetSymbolAddress((void**)&wr,  g_wr);

    cudaFuncSetAttribute(gemm_mma<true>,  cudaFuncAttributeMaxDynamicSharedMemorySize, GSMEM_BYTES);
    cudaFuncSetAttribute(gemm_mma<false>, cudaFuncAttributeMaxDynamicSharedMemorySize, GSMEM_BYTES);
    cudaFuncSetAttribute(flash_tc,        cudaFuncAttributeMaxDynamicSharedMemorySize, FSMEM_BYTES);

    const int xn4 = MROWS * DIMM / 4;
    const int wn4 = WFLOATS / 4;
    round_k<<<xn4 / 256, 256>>>(x,  xr, xn4);
    round_k<<<wn4 / 256, 256>>>(wq, wr + 0 * WFLOATS, wn4);
    round_k<<<wn4 / 256, 256>>>(wk, wr + 1 * WFLOATS, wn4);
    round_k<<<wn4 / 256, 256>>>(wv, wr + 2 * WFLOATS, wn4);
    round_k<<<wn4 / 256, 256>>>(wo, wr + 3 * WFLOATS, wn4);

    gemm_mma<true><<<dim3(DIMM / 128, MROWS / 128, 3), 256, GSMEM_BYTES>>>(
        xr, wr + 0 * WFLOATS, wr + 1 * WFLOATS, wr + 2 * WFLOATS, q, k, v);

    flash_tc<<<dim3(SEQ / 128, BATCH * NHEADS), 256, FSMEM_BYTES>>>(q, k, v, att);

    gemm_mma<false><<<dim3(DIMM / 128, MROWS / 128, 1), 256, GSMEM_BYTES>>>(
        att, wr + 3 * WFLOATS, wr + 3 * WFLOATS, wr + 3 * WFLOATS, out, out, out);
}

// round 6
// speedup vs baseline: 1.5605x; 1.5605x over previous
#include <cuda_runtime.h>
#include <cuda_fp16.h>
#include <cstdint>

#define DIMM   1024
#define NHEADS 16
#define HD     64
#define BATCH  2
#define SEQ    2048
#define MROWS  (BATCH*SEQ)   /* 4096 */
#define WFLOATS (DIMM*DIMM)

// Scratch (allocation-free)
__device__ __half g_qh[MROWS*DIMM];
__device__ __half g_kh[MROWS*DIMM];
__device__ float  g_v [MROWS*DIMM];
__device__ __half g_att[MROWS*DIMM];
__device__ __half g_xh[MROWS*DIMM];
__device__ __half g_wh[4*WFLOATS];

// ===========================================================================
// Helpers
// ===========================================================================
__device__ __forceinline__ uint32_t smem_u32(const void* p) {
    uint32_t a;
    asm("{ .reg .u64 t; cvta.to.shared.u64 t, %1; cvt.u32.u64 %0, t; }" : "=r"(a) : "l"(p));
    return a;
}
__device__ __forceinline__ void cp_async16(uint32_t dst, const void* src) {
    asm volatile("cp.async.cg.shared.global [%0], [%1], 16;" :: "r"(dst), "l"(src) : "memory");
}
#define CP_COMMIT()  asm volatile("cp.async.commit_group;" ::: "memory")
#define CP_WAIT(n)   asm volatile("cp.async.wait_group %0;" :: "n"(n) : "memory")

__device__ __forceinline__ uint32_t f2tf(float f) {
    uint32_t r;
    asm("cvt.rna.tf32.f32 %0, %1;" : "=r"(r) : "f"(f));
    return r;
}
__device__ __forceinline__ uint32_t pack_h2(float a, float b) {
    __half2 h = __floats2half2_rn(a, b);
    return *(uint32_t*)&h;
}
// fp16 m16n8k16: D += A*B
__device__ __forceinline__ void mma16(float* c, const uint32_t* a, const uint32_t* b) {
    asm volatile(
        "mma.sync.aligned.m16n8k16.row.col.f32.f16.f16.f32 "
        "{%0,%1,%2,%3}, {%4,%5,%6,%7}, {%8,%9}, {%0,%1,%2,%3};"
        : "+f"(c[0]), "+f"(c[1]), "+f"(c[2]), "+f"(c[3])
        : "r"(a[0]), "r"(a[1]), "r"(a[2]), "r"(a[3]), "r"(b[0]), "r"(b[1]));
}
// tf32 m16n8k8: D += A*B  (for P@V in flash)
__device__ __forceinline__ void mma8(float* c, const uint32_t* a, const uint32_t* b) {
    asm volatile(
        "mma.sync.aligned.m16n8k8.row.col.f32.tf32.tf32.f32 "
        "{%0,%1,%2,%3}, {%4,%5,%6,%7}, {%8,%9}, {%0,%1,%2,%3};"
        : "+f"(c[0]), "+f"(c[1]), "+f"(c[2]), "+f"(c[3])
        : "r"(a[0]), "r"(a[1]), "r"(a[2]), "r"(a[3]), "r"(b[0]), "r"(b[1]));
}

// FMA-pipe exp: e^(s * 0.125). Clamps low (masked entries -> ~0).
__device__ __forceinline__ float fexp_s(float s) {
    float y = s * 0.18033688011112042f;
    y = fmaxf(y, -100.0f);
    float t = __fadd_rn(y, 12582912.0f);
    float f = __fsub_rn(y, __fsub_rn(t, 12582912.0f));
    int   e = __float_as_int(t) << 23;
    float p = 1.3333558146e-3f;
    p = fmaf(p, f, 9.618129107e-3f);
    p = fmaf(p, f, 5.550410866e-2f);
    p = fmaf(p, f, 2.402265069e-1f);
    p = fmaf(p, f, 6.931471806e-1f);
    p = fmaf(p, f, 1.0f);
    return __int_as_float(__float_as_int(p) + e);
}

// ===========================================================================
// fp32 -> fp16 conversion pass
// ===========================================================================
__global__ __launch_bounds__(256) void round_h(const float* __restrict__ in,
                                               __half* __restrict__ out, int n4)
{
    int i = blockIdx.x * blockDim.x + threadIdx.x;
    if (i < n4) {
        float4 v = ((const float4*)in)[i];
        uint2 w;
        w.x = pack_h2(v.x, v.y);
        w.y = pack_h2(v.z, v.w);
        ((uint2*)out)[i] = w;
    }
}

// ===========================================================================
// fp16 mma.sync GEMM: C[z] = A[M,1024] @ B[z][1024,1024]^T  (half operands)
// CTA 128x128, 8 warps (2m x 4n), BK=32 halves, 2-stage cp.async.
// QKV mode: z0,z1 -> half C; z2 -> fp32 tf32-rounded C. OUT mode: fp32 C.
// ===========================================================================
#define BK    32                       /* halves per ktile */
#define KW    20                       /* words per row (16 data + 4 pad) */
#define GSTAGE_U32 (2*128*KW)
#define GSMEM_BYTES (2 * GSTAGE_U32 * 4)   /* 40960 */
#define KT    (DIMM / BK)                  /* 32 */

template<bool QKV>
__global__ __launch_bounds__(256, 2) void gemm_h(
    const __half* __restrict__ A,
    const __half* __restrict__ B0, const __half* __restrict__ B1, const __half* __restrict__ B2,
    void* __restrict__ C0, void* __restrict__ C1, void* __restrict__ C2)
{
    extern __shared__ uint32_t sm[];
    const int tid  = threadIdx.x;
    const int wid  = tid >> 5;
    const int lane = tid & 31;
    const int wm   = wid >> 2;
    const int wn   = wid & 3;
    const int r0   = lane >> 2;
    const int q4   = lane & 3;

    const __half* Bz = (blockIdx.z == 0) ? B0 : (blockIdx.z == 1) ? B1 : B2;
    void*         Cz = (blockIdx.z == 0) ? C0 : (blockIdx.z == 1) ? C1 : C2;

    const __half* Ag = A  + (size_t)(blockIdx.y * 128) * DIMM;
    const __half* Bg = Bz + (size_t)(blockIdx.x * 128) * DIMM;
    const uint32_t sbase = smem_u32(sm);

    auto load_tile = [&](int kt, int s) {
        uint32_t ab = sbase + s * GSTAGE_U32 * 4;
        uint32_t bb = ab + 128 * KW * 4;
#pragma unroll
        for (int i = 0; i < 2; i++) {
            int idx = i * 256 + tid;
            int row = idx >> 2, seg = idx & 3;
            cp_async16(ab + (row * KW + seg * 4) * 4,
                       Ag + (size_t)row * DIMM + kt * BK + seg * 8);
        }
#pragma unroll
        for (int i = 0; i < 2; i++) {
            int idx = i * 256 + tid;
            int row = idx >> 2, seg = idx & 3;
            cp_async16(bb + (row * KW + seg * 4) * 4,
                       Bg + (size_t)row * DIMM + kt * BK + seg * 8);
        }
        CP_COMMIT();
    };

    float c[4][4][4];
#pragma unroll
    for (int i = 0; i < 4; i++)
#pragma unroll
        for (int j = 0; j < 4; j++)
#pragma unroll
            for (int u = 0; u < 4; u++) c[i][j][u] = 0.f;

    load_tile(0, 0);
    load_tile(1, 1);

    for (int kt = 0; kt < KT; kt++) {
        if (kt + 1 < KT) { CP_WAIT(1); } else { CP_WAIT(0); }
        __syncthreads();
        const uint32_t* Asw = sm + (kt & 1) * GSTAGE_U32;
        const uint32_t* Bsw = Asw + 128 * KW;

#pragma unroll
        for (int st = 0; st < 2; st++) {           // two k16 steps
            const int kw = st * 8 + q4;
            uint32_t a[4][4], b[4][2];
#pragma unroll
            for (int i = 0; i < 4; i++) {
                int r = wm * 64 + i * 16 + r0;
                a[i][0] = Asw[r * KW + kw];
                a[i][1] = Asw[(r + 8) * KW + kw];
                a[i][2] = Asw[r * KW + kw + 4];
                a[i][3] = Asw[(r + 8) * KW + kw + 4];
            }
#pragma unroll
            for (int j = 0; j < 4; j++) {
                int n = wn * 32 + j * 8 + r0;
                b[j][0] = Bsw[n * KW + kw];
                b[j][1] = Bsw[n * KW + kw + 4];
            }
#pragma unroll
            for (int i = 0; i < 4; i++)
#pragma unroll
                for (int j = 0; j < 4; j++)
                    mma16(c[i][j], a[i], b[j]);
        }
        __syncthreads();
        if (kt + 2 < KT) load_tile(kt + 2, kt & 1);
    }

    const size_t crow = (size_t)(blockIdx.y * 128 + wm * 64);
    const int    ccol = blockIdx.x * 128 + wn * 32;
    const bool   as_half = QKV && (blockIdx.z < 2);
#pragma unroll
    for (int i = 0; i < 4; i++)
#pragma unroll
        for (int j = 0; j < 4; j++) {
            int lr  = i * 16 + r0;
            int col = j * 8 + 2 * q4;
            if (as_half) {
                __half* Ch = (__half*)Cz + (crow + lr) * DIMM + ccol + col;
                *(uint32_t*)Ch                = pack_h2(c[i][j][0], c[i][j][1]);
                *(uint32_t*)(Ch + 8 * DIMM)   = pack_h2(c[i][j][2], c[i][j][3]);
            } else if (QKV) {   // v: tf32-rounded fp32
                float* Cf = (float*)Cz + (crow + lr) * DIMM + ccol + col;
                *(float2*)Cf = make_float2(__uint_as_float(f2tf(c[i][j][0])),
                                           __uint_as_float(f2tf(c[i][j][1])));
                *(float2*)(Cf + 8 * DIMM) = make_float2(__uint_as_float(f2tf(c[i][j][2])),
                                                        __uint_as_float(f2tf(c[i][j][3])));
            } else {            // final output: plain fp32
                float* Cf = (float*)Cz + (crow + lr) * DIMM + ccol + col;
                *(float2*)Cf              = make_float2(c[i][j][0], c[i][j][1]);
                *(float2*)(Cf + 8 * DIMM) = make_float2(c[i][j][2], c[i][j][3]);
            }
        }
}

// ===========================================================================
// Fused causal flash attention. QK^T in fp16 mma, P@V in tf32 mma.
// 128 threads, 64 q-rows/CTA (4 warps x 16 rows), Q frags hoisted,
// cp.async double-buffered K/V, reversed qb order. smem 80 KB -> 2 CTAs/SM.
// ===========================================================================
#define QPH 36                  /* half-words per Q/K row (32 data + 4 pad) */
#define PP  68                  /* fp32 words per P row */
#define VP  72                  /* fp32 words per V row */
#define FW_Q  0
#define FW_P  (64*QPH)
#define FW_K  (FW_P + 64*PP)
#define FW_V  (FW_K + 2*64*QPH)
#define FSMEM_WORDS (FW_V + 2*64*VP)
#define FSMEM_BYTES (FSMEM_WORDS * 4)   /* 80384 B */

__global__ __launch_bounds__(128) void flash_h(
    const __half* __restrict__ gq, const __half* __restrict__ gk,
    const float* __restrict__ gv, __half* __restrict__ go)
{
    extern __shared__ uint32_t fsm[];
    uint32_t* Qs = fsm + FW_Q;
    uint32_t* Ps = fsm + FW_P;

    const int qb  = gridDim.x - 1 - blockIdx.x;   // heavy CTAs first
    const int bh  = blockIdx.y;
    const int b   = bh >> 4;
    const int h   = bh & 15;
    const int tid = threadIdx.x;
    const int wid = tid >> 5;
    const int lane = tid & 31;
    const int r0 = lane >> 2;
    const int q4 = lane & 3;
    const size_t hbase = (size_t)b * SEQ * DIMM + (size_t)h * HD;   // in elements
    const uint32_t sbase = smem_u32(fsm);

    auto load_kv = [&](int t) {
        const int s = t & 1;
        const uint32_t kb = sbase + (FW_K + s * 64 * QPH) * 4;
        const uint32_t vb = sbase + (FW_V + s * 64 * VP) * 4;
#pragma unroll
        for (int u = 0; u < 4; u++) {              // K: 64 rows x 8 segs(16B)
            int idx = u * 128 + tid;
            int r = idx >> 3, seg = idx & 7;
            cp_async16(kb + (r * QPH + seg * 4) * 4,
                       gk + hbase + (size_t)(t * 64 + r) * DIMM + seg * 8);
        }
#pragma unroll
        for (int u = 0; u < 8; u++) {              // V: 64 rows x 16 segs(16B)
            int idx = u * 128 + tid;
            int r = idx >> 4, c4 = idx & 15;
            cp_async16(vb + (r * VP + c4 * 4) * 4,
                       gv + hbase + (size_t)(t * 64 + r) * DIMM + c4 * 4);
        }
        CP_COMMIT();
    };

    // Q tile: 64 rows x 64 halves
#pragma unroll
    for (int u = 0; u < 4; u++) {
        int idx = u * 128 + tid;
        int r = idx >> 3, seg = idx & 7;
        uint4 qv = *(const uint4*)(gq + hbase + (size_t)(qb * 64 + r) * DIMM + seg * 8);
        *(uint4*)(Qs + r * QPH + seg * 4) = qv;
    }
    load_kv(0);
    __syncthreads();

    // Hoist Q fragments (4 k16 steps)
    const int arow = wid * 16 + r0;
    uint32_t qf[4][4];
#pragma unroll
    for (int ks = 0; ks < 4; ks++) {
        const int kw = ks * 8 + q4;
        qf[ks][0] = Qs[arow * QPH + kw];
        qf[ks][1] = Qs[(arow + 8) * QPH + kw];
        qf[ks][2] = Qs[arow * QPH + kw + 4];
        qf[ks][3] = Qs[(arow + 8) * QPH + kw + 4];
    }

    float o[8][4];
#pragma unroll
    for (int j = 0; j < 8; j++)
#pragma unroll
        for (int u = 0; u < 4; u++) o[j][u] = 0.f;
    float l0 = 0.f, l1 = 0.f;

    const int grow0 = qb * 64 + arow;
    const int grow1 = grow0 + 8;

    for (int t = 0; t <= qb; t++) {
        if (t + 1 <= qb) load_kv(t + 1);
        if (t < qb) { CP_WAIT(1); } else { CP_WAIT(0); }
        __syncthreads();

        const uint32_t* Ks = fsm + FW_K + (t & 1) * 64 * QPH;
        const uint32_t* Vs = fsm + FW_V + (t & 1) * 64 * VP;

        // ---- S = Q @ K^T (fp16) ----
        float c[8][4];
#pragma unroll
        for (int j = 0; j < 8; j++)
#pragma unroll
            for (int u = 0; u < 4; u++) c[j][u] = 0.f;

#pragma unroll
        for (int ks = 0; ks < 4; ks++) {
            const int kw = ks * 8 + q4;
#pragma unroll
            for (int j = 0; j < 8; j++) {
                uint32_t bf[2];
                int n = j * 8 + r0;
                bf[0] = Ks[n * QPH + kw];
                bf[1] = Ks[n * QPH + kw + 4];
                mma16(c[j], qf[ks], bf);
            }
        }

        // ---- causal mask + exp (FMA pipe; scale folded in) + row sums ----
        const bool diag = (t == qb);
        float s0 = 0.f, s1 = 0.f;
#pragma unroll
        for (int j = 0; j < 8; j++) {
            int col = t * 64 + j * 8 + 2 * q4;
            if (diag) {
                if (col     > grow0) c[j][0] = -1e9f;
                if (col + 1 > grow0) c[j][1] = -1e9f;
                if (col     > grow1) c[j][2] = -1e9f;
                if (col + 1 > grow1) c[j][3] = -1e9f;
            }
            c[j][0] = fexp_s(c[j][0]);
            c[j][1] = fexp_s(c[j][1]);
            c[j][2] = fexp_s(c[j][2]);
            c[j][3] = fexp_s(c[j][3]);
            s0 += c[j][0] + c[j][1];
            s1 += c[j][2] + c[j][3];
        }
        s0 += __shfl_xor_sync(0xffffffffu, s0, 1);
        s0 += __shfl_xor_sync(0xffffffffu, s0, 2);
        s1 += __shfl_xor_sync(0xffffffffu, s1, 1);
        s1 += __shfl_xor_sync(0xffffffffu, s1, 2);
        l0 += s0;
        l1 += s1;

        // ---- P -> smem (tf32), then O += P @ V (tf32) ----
        __syncwarp();
#pragma unroll
        for (int j = 0; j < 8; j++) {
            int pcol = j * 8 + 2 * q4;
            Ps[arow * PP + pcol]           = f2tf(c[j][0]);
            Ps[arow * PP + pcol + 1]       = f2tf(c[j][1]);
            Ps[(arow + 8) * PP + pcol]     = f2tf(c[j][2]);
            Ps[(arow + 8) * PP + pcol + 1] = f2tf(c[j][3]);
        }
        __syncwarp();

#pragma unroll
        for (int ks = 0; ks < 8; ks++) {
            const int k = ks * 8 + q4;
            uint32_t a[4];
            a[0] = Ps[arow * PP + k];
            a[1] = Ps[(arow + 8) * PP + k];
            a[2] = Ps[arow * PP + k + 4];
            a[3] = Ps[(arow + 8) * PP + k + 4];
#pragma unroll
            for (int j = 0; j < 8; j++) {
                uint32_t bf[2];
                int n = j * 8 + r0;
                bf[0] = Vs[(ks * 8 + q4) * VP + n];
                bf[1] = Vs[(ks * 8 + q4 + 4) * VP + n];
                mma8(o[j], a, bf);
            }
        }
        __syncthreads();   // buffer reuse safety
    }

    // ---- normalize + store as half (feeds fp16 out-proj) ----
    const float inv0 = 1.f / l0, inv1 = 1.f / l1;
    const int row0 = qb * 64 + arow;
#pragma unroll
    for (int j = 0; j < 8; j++) {
        int col = j * 8 + 2 * q4;
        __half* p0 = go + hbase + (size_t)row0 * DIMM + col;
        *(uint32_t*)p0              = pack_h2(o[j][0] * inv0, o[j][1] * inv0);
        *(uint32_t*)(p0 + 8 * DIMM) = pack_h2(o[j][2] * inv1, o[j][3] * inv1);
    }
}

// ===========================================================================
extern "C" void kernel_launch(void* const* d_in, const int* in_sizes, int n_in,
                              void* d_out, int out_size)
{
    (void)in_sizes; (void)n_in; (void)out_size;
    const float* x  = (const float*)d_in[0];
    const float* wq = (const float*)d_in[2];
    const float* wk = (const float*)d_in[3];
    const float* wv = (const float*)d_in[4];
    const float* wo = (const float*)d_in[5];
    float* out = (float*)d_out;

    __half *qh, *kh, *att, *xh, *wh;
    float *v;
    cudaGetSymbolAddress((void**)&qh,  g_qh);
    cudaGetSymbolAddress((void**)&kh,  g_kh);
    cudaGetSymbolAddress((void**)&v,   g_v);
    cudaGetSymbolAddress((void**)&att, g_att);
    cudaGetSymbolAddress((void**)&xh,  g_xh);
    cudaGetSymbolAddress((void**)&wh,  g_wh);

    cudaFuncSetAttribute(gemm_h<true>,  cudaFuncAttributeMaxDynamicSharedMemorySize, GSMEM_BYTES);
    cudaFuncSetAttribute(gemm_h<false>, cudaFuncAttributeMaxDynamicSharedMemorySize, GSMEM_BYTES);
    cudaFuncSetAttribute(flash_h,       cudaFuncAttributeMaxDynamicSharedMemorySize, FSMEM_BYTES);

    const int xn4 = MROWS * DIMM / 4;
    const int wn4 = WFLOATS / 4;
    round_h<<<xn4 / 256, 256>>>(x,  xh, xn4);
    round_h<<<wn4 / 256, 256>>>(wq, wh + 0 * WFLOATS, wn4);
    round_h<<<wn4 / 256, 256>>>(wk, wh + 1 * WFLOATS, wn4);
    round_h<<<wn4 / 256, 256>>>(wv, wh + 2 * WFLOATS, wn4);
    round_h<<<wn4 / 256, 256>>>(wo, wh + 3 * WFLOATS, wn4);

    // QKV projection: q,k as half; v as tf32-rounded fp32
    gemm_h<true><<<dim3(DIMM / 128, MROWS / 128, 3), 256, GSMEM_BYTES>>>(
        xh, wh + 0 * WFLOATS, wh + 1 * WFLOATS, wh + 2 * WFLOATS, qh, kh, v);

    flash_h<<<dim3(SEQ / 64, BATCH * NHEADS), 128, FSMEM_BYTES>>>(qh, kh, v, att);

    // Output projection (fp32 result)
    gemm_h<false><<<dim3(DIMM / 128, MROWS / 128, 1), 256, GSMEM_BYTES>>>(
        att, wh + 3 * WFLOATS, wh + 3 * WFLOATS, wh + 3 * WFLOATS, out, out, out);
}

// round 8
// speedup vs baseline: 2.0733x; 1.3286x over previous
#include <cuda_runtime.h>
#include <cuda_fp16.h>
#include <cstdint>

#define DIMM   1024
#define NHEADS 16
#define HD     64
#define BATCH  2
#define SEQ    2048
#define MROWS  (BATCH*SEQ)   /* 4096 */
#define WFLOATS (DIMM*DIMM)

// Scratch (allocation-free)
__device__ __half g_qh[MROWS*DIMM];
__device__ __half g_kh[MROWS*DIMM];
__device__ __half g_vh[MROWS*DIMM];
__device__ __half g_att[MROWS*DIMM];
__device__ __half g_xh[MROWS*DIMM];
__device__ __half g_wh[4*WFLOATS];

// ===========================================================================
// Helpers
// ===========================================================================
__device__ __forceinline__ uint32_t smem_u32(const void* p) {
    uint32_t a;
    asm("{ .reg .u64 t; cvta.to.shared.u64 t, %1; cvt.u32.u64 %0, t; }" : "=r"(a) : "l"(p));
    return a;
}
__device__ __forceinline__ void cp_async16(uint32_t dst, const void* src) {
    asm volatile("cp.async.cg.shared.global [%0], [%1], 16;" :: "r"(dst), "l"(src) : "memory");
}
#define CP_COMMIT()  asm volatile("cp.async.commit_group;" ::: "memory")
#define CP_WAIT(n)   asm volatile("cp.async.wait_group %0;" :: "n"(n) : "memory")

__device__ __forceinline__ uint32_t pack_h2(float a, float b) {
    __half2 h = __floats2half2_rn(a, b);
    return *(uint32_t*)&h;
}
// fp16 m16n8k16: D += A*B
__device__ __forceinline__ void mma16(float* c, const uint32_t* a, const uint32_t* b) {
    asm volatile(
        "mma.sync.aligned.m16n8k16.row.col.f32.f16.f16.f32 "
        "{%0,%1,%2,%3}, {%4,%5,%6,%7}, {%8,%9}, {%0,%1,%2,%3};"
        : "+f"(c[0]), "+f"(c[1]), "+f"(c[2]), "+f"(c[3])
        : "r"(a[0]), "r"(a[1]), "r"(a[2]), "r"(a[3]), "r"(b[0]), "r"(b[1]));
}
__device__ __forceinline__ void ldsm4(uint32_t& r0, uint32_t& r1, uint32_t& r2, uint32_t& r3,
                                      uint32_t addr) {
    asm volatile("ldmatrix.sync.aligned.m8n8.x4.shared.b16 {%0,%1,%2,%3}, [%4];"
                 : "=r"(r0), "=r"(r1), "=r"(r2), "=r"(r3) : "r"(addr));
}
__device__ __forceinline__ void ldsm4t(uint32_t& r0, uint32_t& r1, uint32_t& r2, uint32_t& r3,
                                       uint32_t addr) {
    asm volatile("ldmatrix.sync.aligned.m8n8.x4.trans.shared.b16 {%0,%1,%2,%3}, [%4];"
                 : "=r"(r0), "=r"(r1), "=r"(r2), "=r"(r3) : "r"(addr));
}

// FMA-pipe exp: e^(s * 0.125). Clamps low (masked entries -> ~0).
__device__ __forceinline__ float fexp_s(float s) {
    float y = s * 0.18033688011112042f;
    y = fmaxf(y, -100.0f);
    float t = __fadd_rn(y, 12582912.0f);
    float f = __fsub_rn(y, __fsub_rn(t, 12582912.0f));
    int   e = __float_as_int(t) << 23;
    float p = 1.3333558146e-3f;
    p = fmaf(p, f, 9.618129107e-3f);
    p = fmaf(p, f, 5.550410866e-2f);
    p = fmaf(p, f, 2.402265069e-1f);
    p = fmaf(p, f, 6.931471806e-1f);
    p = fmaf(p, f, 1.0f);
    return __int_as_float(__float_as_int(p) + e);
}

// ===========================================================================
// fp32 -> fp16 conversion passes
// ===========================================================================
__global__ __launch_bounds__(256) void round_h(const float* __restrict__ in,
                                               __half* __restrict__ out, int n4)
{
    int i = blockIdx.x * blockDim.x + threadIdx.x;
    if (i < n4) {
        float4 v = ((const float4*)in)[i];
        uint2 w;
        w.x = pack_h2(v.x, v.y);
        w.y = pack_h2(v.z, v.w);
        ((uint2*)out)[i] = w;
    }
}
__global__ __launch_bounds__(256) void round_h4(
    const float* __restrict__ w0, const float* __restrict__ w1,
    const float* __restrict__ w2, const float* __restrict__ w3,
    __half* __restrict__ out, int n4)
{
    const float* in = (blockIdx.y == 0) ? w0 : (blockIdx.y == 1) ? w1 :
                      (blockIdx.y == 2) ? w2 : w3;
    __half* o = out + (size_t)blockIdx.y * WFLOATS;
    int i = blockIdx.x * blockDim.x + threadIdx.x;
    if (i < n4) {
        float4 v = ((const float4*)in)[i];
        uint2 w;
        w.x = pack_h2(v.x, v.y);
        w.y = pack_h2(v.z, v.w);
        ((uint2*)o)[i] = w;
    }
}

// ===========================================================================
// fp16 mma.sync GEMM with ldmatrix fragments.
// CTA 128x128, 8 warps (2m x 4n), BK=32 halves, 2-stage cp.async.
// ===========================================================================
#define BK    32
#define KW    20                       /* u32 words per row (16 data + 4 pad); 80 B = 16B-aligned */
#define GSTAGE_U32 (2*128*KW)
#define GSMEM_BYTES (2 * GSTAGE_U32 * 4)   /* 40960 */
#define KT    (DIMM / BK)

template<bool HALF_OUT>
__global__ __launch_bounds__(256, 2) void gemm_h(
    const __half* __restrict__ A,
    const __half* __restrict__ B0, const __half* __restrict__ B1, const __half* __restrict__ B2,
    void* __restrict__ C0, void* __restrict__ C1, void* __restrict__ C2)
{
    extern __shared__ uint32_t sm[];
    const int tid  = threadIdx.x;
    const int wid  = tid >> 5;
    const int lane = tid & 31;
    const int wm   = wid >> 2;
    const int wn   = wid & 3;
    const int r0   = lane >> 2;
    const int q4   = lane & 3;
    const int g    = lane >> 3;        // ldmatrix quad group
    const int lr   = lane & 7;

    const __half* Bz = (blockIdx.z == 0) ? B0 : (blockIdx.z == 1) ? B1 : B2;
    void*         Cz = (blockIdx.z == 0) ? C0 : (blockIdx.z == 1) ? C1 : C2;

    const __half* Ag = A  + (size_t)(blockIdx.y * 128) * DIMM;
    const __half* Bg = Bz + (size_t)(blockIdx.x * 128) * DIMM;
    const uint32_t sbase = smem_u32(sm);

    // per-lane ldmatrix byte offsets (within a stage)
    const uint32_t a_off = ((wm * 64 + (g & 1) * 8 + lr) * KW + (g >> 1) * 4) * 4;
    const uint32_t b_off = (128 * KW + (wn * 32 + (g >> 1) * 8 + lr) * KW + (g & 1) * 4) * 4;

    auto load_tile = [&](int kt, int s) {
        uint32_t ab = sbase + s * GSTAGE_U32 * 4;
        uint32_t bb = ab + 128 * KW * 4;
#pragma unroll
        for (int i = 0; i < 2; i++) {
            int idx = i * 256 + tid;
            int row = idx >> 2, seg = idx & 3;
            cp_async16(ab + (row * KW + seg * 4) * 4,
                       Ag + (size_t)row * DIMM + kt * BK + seg * 8);
        }
#pragma unroll
        for (int i = 0; i < 2; i++) {
            int idx = i * 256 + tid;
            int row = idx >> 2, seg = idx & 3;
            cp_async16(bb + (row * KW + seg * 4) * 4,
                       Bg + (size_t)row * DIMM + kt * BK + seg * 8);
        }
        CP_COMMIT();
    };

    float c[4][4][4];
#pragma unroll
    for (int i = 0; i < 4; i++)
#pragma unroll
        for (int j = 0; j < 4; j++)
#pragma unroll
            for (int u = 0; u < 4; u++) c[i][j][u] = 0.f;

    load_tile(0, 0);
    load_tile(1, 1);

    for (int kt = 0; kt < KT; kt++) {
        if (kt + 1 < KT) { CP_WAIT(1); } else { CP_WAIT(0); }
        __syncthreads();
        const uint32_t stage = sbase + (kt & 1) * GSTAGE_U32 * 4;

#pragma unroll
        for (int st = 0; st < 2; st++) {
            const uint32_t koff = st * 8 * 4;      // st*16 halves = st*8 words
            uint32_t a[4][4], b[4][2];
#pragma unroll
            for (int i = 0; i < 4; i++)
                ldsm4(a[i][0], a[i][1], a[i][2], a[i][3],
                      stage + a_off + (i * 16 * KW) * 4 + koff);
#pragma unroll
            for (int jp = 0; jp < 2; jp++)
                ldsm4(b[2*jp][0], b[2*jp][1], b[2*jp+1][0], b[2*jp+1][1],
                      stage + b_off + (jp * 16 * KW) * 4 + koff);
#pragma unroll
            for (int i = 0; i < 4; i++)
#pragma unroll
                for (int j = 0; j < 4; j++)
                    mma16(c[i][j], a[i], b[j]);
        }
        __syncthreads();
        if (kt + 2 < KT) load_tile(kt + 2, kt & 1);
    }

    const size_t crow = (size_t)(blockIdx.y * 128 + wm * 64);
    const int    ccol = blockIdx.x * 128 + wn * 32;
#pragma unroll
    for (int i = 0; i < 4; i++)
#pragma unroll
        for (int j = 0; j < 4; j++) {
            int lrr = i * 16 + r0;
            int col = j * 8 + 2 * q4;
            if (HALF_OUT) {
                __half* Ch = (__half*)Cz + (crow + lrr) * DIMM + ccol + col;
                *(uint32_t*)Ch              = pack_h2(c[i][j][0], c[i][j][1]);
                *(uint32_t*)(Ch + 8 * DIMM) = pack_h2(c[i][j][2], c[i][j][3]);
            } else {
                float* Cf = (float*)Cz + (crow + lrr) * DIMM + ccol + col;
                *(float2*)Cf              = make_float2(c[i][j][0], c[i][j][1]);
                *(float2*)(Cf + 8 * DIMM) = make_float2(c[i][j][2], c[i][j][3]);
            }
        }
}

// ===========================================================================
// Fused causal flash attention, all-fp16 mma with ldmatrix fragments.
// 128 threads, 64 q-rows/CTA, Q frags hoisted, double-buffered K/V.
// All row strides are 16B multiples (ldmatrix requirement).
// ===========================================================================
#define QPH 36   /* u32 words per Q/K row: 144 B, 16B-aligned */
#define PPH 36   /* u32 words per P row: 144 B (was 34 -> misaligned trap) */
#define VPH 36   /* u32 words per V row */
#define FW_Q  0
#define FW_P  (64*QPH)
#define FW_K  (FW_P + 64*PPH)
#define FW_V  (FW_K + 2*64*QPH)
#define FSMEM_WORDS (FW_V + 2*64*VPH)
#define FSMEM_BYTES (FSMEM_WORDS * 4)   /* 55296 */

__global__ __launch_bounds__(128) void flash_h(
    const __half* __restrict__ gq, const __half* __restrict__ gk,
    const __half* __restrict__ gv, __half* __restrict__ go)
{
    extern __shared__ uint32_t fsm[];
    uint32_t* Qs = fsm + FW_Q;
    uint32_t* Ps = fsm + FW_P;

    const int qb  = gridDim.x - 1 - blockIdx.x;   // heavy CTAs first
    const int bh  = blockIdx.y;
    const int b   = bh >> 4;
    const int h   = bh & 15;
    const int tid = threadIdx.x;
    const int wid = tid >> 5;
    const int lane = tid & 31;
    const int r0 = lane >> 2;
    const int q4 = lane & 3;
    const int g  = lane >> 3;
    const int lr = lane & 7;
    const size_t hbase = (size_t)b * SEQ * DIMM + (size_t)h * HD;
    const uint32_t sbase = smem_u32(fsm);

    // per-lane ldmatrix byte offsets
    const uint32_t koff_b = (((g >> 1) * 8 + lr) * QPH + (g & 1) * 4) * 4;  // K frag (non-trans)
    const uint32_t voff_b = (((g & 1) * 8 + lr) * VPH + (g >> 1) * 4) * 4;  // V frag (trans)
    const uint32_t poff_a = ((wid * 16 + (g & 1) * 8 + lr) * PPH + (g >> 1) * 4) * 4;

    auto load_kv = [&](int t) {
        const int s = t & 1;
        const uint32_t kb = sbase + (FW_K + s * 64 * QPH) * 4;
        const uint32_t vb = sbase + (FW_V + s * 64 * VPH) * 4;
#pragma unroll
        for (int u = 0; u < 4; u++) {
            int idx = u * 128 + tid;
            int r = idx >> 3, seg = idx & 7;
            cp_async16(kb + (r * QPH + seg * 4) * 4,
                       gk + hbase + (size_t)(t * 64 + r) * DIMM + seg * 8);
            cp_async16(vb + (r * VPH + seg * 4) * 4,
                       gv + hbase + (size_t)(t * 64 + r) * DIMM + seg * 8);
        }
        CP_COMMIT();
    };

    // Q tile
#pragma unroll
    for (int u = 0; u < 4; u++) {
        int idx = u * 128 + tid;
        int r = idx >> 3, seg = idx & 7;
        uint4 qv = *(const uint4*)(gq + hbase + (size_t)(qb * 64 + r) * DIMM + seg * 8);
        *(uint4*)(Qs + r * QPH + seg * 4) = qv;
    }
    load_kv(0);
    __syncthreads();

    // Hoist Q fragments (4 k16 steps)
    const int arow = wid * 16 + r0;
    uint32_t qf[4][4];
#pragma unroll
    for (int ks = 0; ks < 4; ks++) {
        const int kw = ks * 8 + q4;
        qf[ks][0] = Qs[arow * QPH + kw];
        qf[ks][1] = Qs[(arow + 8) * QPH + kw];
        qf[ks][2] = Qs[arow * QPH + kw + 4];
        qf[ks][3] = Qs[(arow + 8) * QPH + kw + 4];
    }

    float o[8][4];
#pragma unroll
    for (int j = 0; j < 8; j++)
#pragma unroll
        for (int u = 0; u < 4; u++) o[j][u] = 0.f;
    float l0 = 0.f, l1 = 0.f;

    const int grow0 = qb * 64 + arow;
    const int grow1 = grow0 + 8;

    for (int t = 0; t <= qb; t++) {
        if (t + 1 <= qb) load_kv(t + 1);
        if (t < qb) { CP_WAIT(1); } else { CP_WAIT(0); }
        __syncthreads();

        const uint32_t kbase = sbase + (FW_K + (t & 1) * 64 * QPH) * 4;
        const uint32_t vbase = sbase + (FW_V + (t & 1) * 64 * VPH) * 4;

        // ---- S = Q @ K^T (fp16, ldmatrix B) ----
        float c[8][4];
#pragma unroll
        for (int j = 0; j < 8; j++)
#pragma unroll
            for (int u = 0; u < 4; u++) c[j][u] = 0.f;

#pragma unroll
        for (int ks = 0; ks < 4; ks++) {
            uint32_t b[8][2];
#pragma unroll
            for (int jp = 0; jp < 4; jp++)
                ldsm4(b[2*jp][0], b[2*jp][1], b[2*jp+1][0], b[2*jp+1][1],
                      kbase + koff_b + (jp * 16 * QPH + ks * 8) * 4);
#pragma unroll
            for (int j = 0; j < 8; j++)
                mma16(c[j], qf[ks], b[j]);
        }

        // ---- causal mask + exp (FMA pipe; scale folded in) + row sums ----
        const bool diag = (t == qb);
        float s0 = 0.f, s1 = 0.f;
#pragma unroll
        for (int j = 0; j < 8; j++) {
            int col = t * 64 + j * 8 + 2 * q4;
            if (diag) {
                if (col     > grow0) c[j][0] = -1e9f;
                if (col + 1 > grow0) c[j][1] = -1e9f;
                if (col     > grow1) c[j][2] = -1e9f;
                if (col + 1 > grow1) c[j][3] = -1e9f;
            }
            c[j][0] = fexp_s(c[j][0]);
            c[j][1] = fexp_s(c[j][1]);
            c[j][2] = fexp_s(c[j][2]);
            c[j][3] = fexp_s(c[j][3]);
            s0 += c[j][0] + c[j][1];
            s1 += c[j][2] + c[j][3];
        }
        s0 += __shfl_xor_sync(0xffffffffu, s0, 1);
        s0 += __shfl_xor_sync(0xffffffffu, s0, 2);
        s1 += __shfl_xor_sync(0xffffffffu, s1, 1);
        s1 += __shfl_xor_sync(0xffffffffu, s1, 2);
        l0 += s0;
        l1 += s1;

        // ---- P -> smem (half2 words), then O += P @ V (fp16) ----
        __syncwarp();
#pragma unroll
        for (int j = 0; j < 8; j++) {
            int pw = j * 4 + q4;
            Ps[arow * PPH + pw]       = pack_h2(c[j][0], c[j][1]);
            Ps[(arow + 8) * PPH + pw] = pack_h2(c[j][2], c[j][3]);
        }
        __syncwarp();

#pragma unroll
        for (int ks = 0; ks < 4; ks++) {
            uint32_t a[4], b[8][2];
            ldsm4(a[0], a[1], a[2], a[3],
                  sbase + FW_P * 4 + poff_a + (ks * 8) * 4);
#pragma unroll
            for (int jp = 0; jp < 4; jp++)
                ldsm4t(b[2*jp][0], b[2*jp][1], b[2*jp+1][0], b[2*jp+1][1],
                       vbase + voff_b + (ks * 16 * VPH + jp * 8) * 4);
#pragma unroll
            for (int j = 0; j < 8; j++)
                mma16(o[j], a, b[j]);
        }
        __syncthreads();   // buffer reuse safety
    }

    // ---- normalize + store as half ----
    const float inv0 = 1.f / l0, inv1 = 1.f / l1;
    const int row0 = qb * 64 + arow;
#pragma unroll
    for (int j = 0; j < 8; j++) {
        int col = j * 8 + 2 * q4;
        __half* p0 = go + hbase + (size_t)row0 * DIMM + col;
        *(uint32_t*)p0              = pack_h2(o[j][0] * inv0, o[j][1] * inv0);
        *(uint32_t*)(p0 + 8 * DIMM) = pack_h2(o[j][2] * inv1, o[j][3] * inv1);
    }
}

// ===========================================================================
extern "C" void kernel_launch(void* const* d_in, const int* in_sizes, int n_in,
                              void* d_out, int out_size)
{
    (void)in_sizes; (void)n_in; (void)out_size;
    const float* x  = (const float*)d_in[0];
    const float* wq = (const float*)d_in[2];
    const float* wk = (const float*)d_in[3];
    const float* wv = (const float*)d_in[4];
    const float* wo = (const float*)d_in[5];
    float* out = (float*)d_out;

    __half *qh, *kh, *vh, *att, *xh, *wh;
    cudaGetSymbolAddress((void**)&qh,  g_qh);
    cudaGetSymbolAddress((void**)&kh,  g_kh);
    cudaGetSymbolAddress((void**)&vh,  g_vh);
    cudaGetSymbolAddress((void**)&att, g_att);
    cudaGetSymbolAddress((void**)&xh,  g_xh);
    cudaGetSymbolAddress((void**)&wh,  g_wh);

    cudaFuncSetAttribute(gemm_h<true>,  cudaFuncAttributeMaxDynamicSharedMemorySize, GSMEM_BYTES);
    cudaFuncSetAttribute(gemm_h<false>, cudaFuncAttributeMaxDynamicSharedMemorySize, GSMEM_BYTES);
    cudaFuncSetAttribute(flash_h,       cudaFuncAttributeMaxDynamicSharedMemorySize, FSMEM_BYTES);

    const int xn4 = MROWS * DIMM / 4;
    const int wn4 = WFLOATS / 4;
    round_h<<<xn4 / 256, 256>>>(x, xh, xn4);
    round_h4<<<dim3(wn4 / 256, 4), 256>>>(wq, wk, wv, wo, wh, wn4);

    // QKV projection: all outputs half
    gemm_h<true><<<dim3(DIMM / 128, MROWS / 128, 3), 256, GSMEM_BYTES>>>(
        xh, wh + 0 * WFLOATS, wh + 1 * WFLOATS, wh + 2 * WFLOATS, qh, kh, vh);

    flash_h<<<dim3(SEQ / 64, BATCH * NHEADS), 128, FSMEM_BYTES>>>(qh, kh, vh, att);

    // Output projection (fp32 result)
    gemm_h<false><<<dim3(DIMM / 128, MROWS / 128, 1), 256, GSMEM_BYTES>>>(
        att, wh + 3 * WFLOATS, wh + 3 * WFLOATS, wh + 3 * WFLOATS, out, out, out);
}

// round 9
// speedup vs baseline: 2.1052x; 1.0154x over previous
#include <cuda_runtime.h>
#include <cuda_fp16.h>
#include <cstdint>

#define DIMM   1024
#define NHEADS 16
#define HD     64
#define BATCH  2
#define SEQ    2048
#define MROWS  (BATCH*SEQ)   /* 4096 */
#define WFLOATS (DIMM*DIMM)

// Scratch (allocation-free)
__device__ __half g_qh[MROWS*DIMM];
__device__ __half g_kh[MROWS*DIMM];
__device__ __half g_vh[MROWS*DIMM];
__device__ __half g_att[MROWS*DIMM];
__device__ __half g_xh[MROWS*DIMM];
__device__ __half g_wh[4*WFLOATS];

// ===========================================================================
// Helpers
// ===========================================================================
__device__ __forceinline__ uint32_t smem_u32(const void* p) {
    uint32_t a;
    asm("{ .reg .u64 t; cvta.to.shared.u64 t, %1; cvt.u32.u64 %0, t; }" : "=r"(a) : "l"(p));
    return a;
}
__device__ __forceinline__ void cp_async16(uint32_t dst, const void* src) {
    asm volatile("cp.async.cg.shared.global [%0], [%1], 16;" :: "r"(dst), "l"(src) : "memory");
}
#define CP_COMMIT()  asm volatile("cp.async.commit_group;" ::: "memory")
#define CP_WAIT(n)   asm volatile("cp.async.wait_group %0;" :: "n"(n) : "memory")

__device__ __forceinline__ uint32_t pack_h2(float a, float b) {
    __half2 h = __floats2half2_rn(a, b);
    return *(uint32_t*)&h;
}
// fp16 m16n8k16: D += A*B
__device__ __forceinline__ void mma16(float* c, const uint32_t* a, const uint32_t* b) {
    asm volatile(
        "mma.sync.aligned.m16n8k16.row.col.f32.f16.f16.f32 "
        "{%0,%1,%2,%3}, {%4,%5,%6,%7}, {%8,%9}, {%0,%1,%2,%3};"
        : "+f"(c[0]), "+f"(c[1]), "+f"(c[2]), "+f"(c[3])
        : "r"(a[0]), "r"(a[1]), "r"(a[2]), "r"(a[3]), "r"(b[0]), "r"(b[1]));
}
__device__ __forceinline__ void ldsm4(uint32_t& r0, uint32_t& r1, uint32_t& r2, uint32_t& r3,
                                      uint32_t addr) {
    asm volatile("ldmatrix.sync.aligned.m8n8.x4.shared.b16 {%0,%1,%2,%3}, [%4];"
                 : "=r"(r0), "=r"(r1), "=r"(r2), "=r"(r3) : "r"(addr));
}
__device__ __forceinline__ void ldsm4t(uint32_t& r0, uint32_t& r1, uint32_t& r2, uint32_t& r3,
                                       uint32_t addr) {
    asm volatile("ldmatrix.sync.aligned.m8n8.x4.trans.shared.b16 {%0,%1,%2,%3}, [%4];"
                 : "=r"(r0), "=r"(r1), "=r"(r2), "=r"(r3) : "r"(addr));
}

// FMA-pipe exp: e^(s * 0.125). Clamps low (masked entries -> ~0).
__device__ __forceinline__ float fexp_s(float s) {
    float y = s * 0.18033688011112042f;
    y = fmaxf(y, -100.0f);
    float t = __fadd_rn(y, 12582912.0f);
    float f = __fsub_rn(y, __fsub_rn(t, 12582912.0f));
    int   e = __float_as_int(t) << 23;
    float p = 1.3333558146e-3f;
    p = fmaf(p, f, 9.618129107e-3f);
    p = fmaf(p, f, 5.550410866e-2f);
    p = fmaf(p, f, 2.402265069e-1f);
    p = fmaf(p, f, 6.931471806e-1f);
    p = fmaf(p, f, 1.0f);
    return __int_as_float(__float_as_int(p) + e);
}

// ===========================================================================
// fp32 -> fp16 conversion passes
// ===========================================================================
__global__ __launch_bounds__(256) void round_h(const float* __restrict__ in,
                                               __half* __restrict__ out, int n4)
{
    int i = blockIdx.x * blockDim.x + threadIdx.x;
    if (i < n4) {
        float4 v = ((const float4*)in)[i];
        uint2 w;
        w.x = pack_h2(v.x, v.y);
        w.y = pack_h2(v.z, v.w);
        ((uint2*)out)[i] = w;
    }
}
__global__ __launch_bounds__(256) void round_h4(
    const float* __restrict__ w0, const float* __restrict__ w1,
    const float* __restrict__ w2, const float* __restrict__ w3,
    __half* __restrict__ out, int n4)
{
    const float* in = (blockIdx.y == 0) ? w0 : (blockIdx.y == 1) ? w1 :
                      (blockIdx.y == 2) ? w2 : w3;
    __half* o = out + (size_t)blockIdx.y * WFLOATS;
    int i = blockIdx.x * blockDim.x + threadIdx.x;
    if (i < n4) {
        float4 v = ((const float4*)in)[i];
        uint2 w;
        w.x = pack_h2(v.x, v.y);
        w.y = pack_h2(v.z, v.w);
        ((uint2*)o)[i] = w;
    }
}

// ===========================================================================
// fp16 mma.sync GEMM with ldmatrix fragments.
// CTA 128x128, 8 warps (2m x 4n), BK=32 halves, 3-stage cp.async.
// ===========================================================================
#define BK    32
#define KW    20                       /* u32 words per row (16 data + 4 pad) */
#define GST   3
#define GSTAGE_U32 (2*128*KW)
#define GSMEM_BYTES (GST * GSTAGE_U32 * 4)   /* 61440 */
#define KT    (DIMM / BK)

template<bool HALF_OUT>
__global__ __launch_bounds__(256, 2) void gemm_h(
    const __half* __restrict__ A,
    const __half* __restrict__ B0, const __half* __restrict__ B1, const __half* __restrict__ B2,
    void* __restrict__ C0, void* __restrict__ C1, void* __restrict__ C2)
{
    extern __shared__ uint32_t sm[];
    const int tid  = threadIdx.x;
    const int wid  = tid >> 5;
    const int lane = tid & 31;
    const int wm   = wid >> 2;
    const int wn   = wid & 3;
    const int r0   = lane >> 2;
    const int q4   = lane & 3;
    const int g    = lane >> 3;
    const int lr   = lane & 7;

    const __half* Bz = (blockIdx.z == 0) ? B0 : (blockIdx.z == 1) ? B1 : B2;
    void*         Cz = (blockIdx.z == 0) ? C0 : (blockIdx.z == 1) ? C1 : C2;

    const __half* Ag = A  + (size_t)(blockIdx.y * 128) * DIMM;
    const __half* Bg = Bz + (size_t)(blockIdx.x * 128) * DIMM;
    const uint32_t sbase = smem_u32(sm);

    const uint32_t a_off = ((wm * 64 + (g & 1) * 8 + lr) * KW + (g >> 1) * 4) * 4;
    const uint32_t b_off = (128 * KW + (wn * 32 + (g >> 1) * 8 + lr) * KW + (g & 1) * 4) * 4;

    auto load_tile = [&](int kt, int s) {
        uint32_t ab = sbase + s * GSTAGE_U32 * 4;
        uint32_t bb = ab + 128 * KW * 4;
#pragma unroll
        for (int i = 0; i < 2; i++) {
            int idx = i * 256 + tid;
            int row = idx >> 2, seg = idx & 3;
            cp_async16(ab + (row * KW + seg * 4) * 4,
                       Ag + (size_t)row * DIMM + kt * BK + seg * 8);
        }
#pragma unroll
        for (int i = 0; i < 2; i++) {
            int idx = i * 256 + tid;
            int row = idx >> 2, seg = idx & 3;
            cp_async16(bb + (row * KW + seg * 4) * 4,
                       Bg + (size_t)row * DIMM + kt * BK + seg * 8);
        }
        CP_COMMIT();
    };

    float c[4][4][4];
#pragma unroll
    for (int i = 0; i < 4; i++)
#pragma unroll
        for (int j = 0; j < 4; j++)
#pragma unroll
            for (int u = 0; u < 4; u++) c[i][j][u] = 0.f;

    load_tile(0, 0);
    load_tile(1, 1);
    load_tile(2, 2);

    for (int kt = 0; kt < KT; kt++) {
        CP_WAIT(2);                        // 3 groups always outstanding
        __syncthreads();
        const uint32_t stage = sbase + (kt % GST) * GSTAGE_U32 * 4;

#pragma unroll
        for (int st = 0; st < 2; st++) {
            const uint32_t koff = st * 8 * 4;
            uint32_t a[4][4], b[4][2];
#pragma unroll
            for (int i = 0; i < 4; i++)
                ldsm4(a[i][0], a[i][1], a[i][2], a[i][3],
                      stage + a_off + (i * 16 * KW) * 4 + koff);
#pragma unroll
            for (int jp = 0; jp < 2; jp++)
                ldsm4(b[2*jp][0], b[2*jp][1], b[2*jp+1][0], b[2*jp+1][1],
                      stage + b_off + (jp * 16 * KW) * 4 + koff);
#pragma unroll
            for (int i = 0; i < 4; i++)
#pragma unroll
                for (int j = 0; j < 4; j++)
                    mma16(c[i][j], a[i], b[j]);
        }
        __syncthreads();
        if (kt + GST < KT) load_tile(kt + GST, kt % GST);
        else               CP_COMMIT();    // empty group keeps count invariant
    }

    const size_t crow = (size_t)(blockIdx.y * 128 + wm * 64);
    const int    ccol = blockIdx.x * 128 + wn * 32;
#pragma unroll
    for (int i = 0; i < 4; i++)
#pragma unroll
        for (int j = 0; j < 4; j++) {
            int lrr = i * 16 + r0;
            int col = j * 8 + 2 * q4;
            if (HALF_OUT) {
                __half* Ch = (__half*)Cz + (crow + lrr) * DIMM + ccol + col;
                *(uint32_t*)Ch              = pack_h2(c[i][j][0], c[i][j][1]);
                *(uint32_t*)(Ch + 8 * DIMM) = pack_h2(c[i][j][2], c[i][j][3]);
            } else {
                float* Cf = (float*)Cz + (crow + lrr) * DIMM + ccol + col;
                *(float2*)Cf              = make_float2(c[i][j][0], c[i][j][1]);
                *(float2*)(Cf + 8 * DIMM) = make_float2(c[i][j][2], c[i][j][3]);
            }
        }
}

// ===========================================================================
// Fused causal flash attention, all-fp16 mma with ldmatrix fragments.
// 128 threads, 64 q-rows/CTA. P buffer ALIASES the dead Q buffer (Q is
// register-resident after the hoist) -> smem 46 KB; launch_bounds(128,4)
// -> 4 CTAs/SM.
// ===========================================================================
#define QPH 36   /* u32 words per Q/K/P/V row: 144 B, 16B-aligned */
#define VPH 36
#define FW_QP 0                    /* Q tile, later reused as P */
#define FW_K  (64*QPH)
#define FW_V  (FW_K + 2*64*QPH)
#define FSMEM_WORDS (FW_V + 2*64*VPH)
#define FSMEM_BYTES (FSMEM_WORDS * 4)   /* 46080 */

__global__ __launch_bounds__(128, 4) void flash_h(
    const __half* __restrict__ gq, const __half* __restrict__ gk,
    const __half* __restrict__ gv, __half* __restrict__ go)
{
    extern __shared__ uint32_t fsm[];
    uint32_t* QPs = fsm + FW_QP;       // Q during prologue, P during loop

    const int qb  = gridDim.x - 1 - blockIdx.x;   // heavy CTAs first
    const int bh  = blockIdx.y;
    const int b   = bh >> 4;
    const int h   = bh & 15;
    const int tid = threadIdx.x;
    const int wid = tid >> 5;
    const int lane = tid & 31;
    const int r0 = lane >> 2;
    const int q4 = lane & 3;
    const int g  = lane >> 3;
    const int lr = lane & 7;
    const size_t hbase = (size_t)b * SEQ * DIMM + (size_t)h * HD;
    const uint32_t sbase = smem_u32(fsm);

    const uint32_t koff_b = (((g >> 1) * 8 + lr) * QPH + (g & 1) * 4) * 4;
    const uint32_t voff_b = (((g & 1) * 8 + lr) * VPH + (g >> 1) * 4) * 4;
    const uint32_t poff_a = ((wid * 16 + (g & 1) * 8 + lr) * QPH + (g >> 1) * 4) * 4;

    auto load_kv = [&](int t) {
        const int s = t & 1;
        const uint32_t kb = sbase + (FW_K + s * 64 * QPH) * 4;
        const uint32_t vb = sbase + (FW_V + s * 64 * VPH) * 4;
#pragma unroll
        for (int u = 0; u < 4; u++) {
            int idx = u * 128 + tid;
            int r = idx >> 3, seg = idx & 7;
            cp_async16(kb + (r * QPH + seg * 4) * 4,
                       gk + hbase + (size_t)(t * 64 + r) * DIMM + seg * 8);
            cp_async16(vb + (r * VPH + seg * 4) * 4,
                       gv + hbase + (size_t)(t * 64 + r) * DIMM + seg * 8);
        }
        CP_COMMIT();
    };

    // Q tile -> smem (transient)
#pragma unroll
    for (int u = 0; u < 4; u++) {
        int idx = u * 128 + tid;
        int r = idx >> 3, seg = idx & 7;
        uint4 qv = *(const uint4*)(gq + hbase + (size_t)(qb * 64 + r) * DIMM + seg * 8);
        *(uint4*)(QPs + r * QPH + seg * 4) = qv;
    }
    load_kv(0);
    __syncthreads();

    // Hoist Q fragments; Q smem is dead afterwards (P reuses it).
    const int arow = wid * 16 + r0;
    uint32_t qf[4][4];
#pragma unroll
    for (int ks = 0; ks < 4; ks++) {
        const int kw = ks * 8 + q4;
        qf[ks][0] = QPs[arow * QPH + kw];
        qf[ks][1] = QPs[(arow + 8) * QPH + kw];
        qf[ks][2] = QPs[arow * QPH + kw + 4];
        qf[ks][3] = QPs[(arow + 8) * QPH + kw + 4];
    }

    float o[8][4];
#pragma unroll
    for (int j = 0; j < 8; j++)
#pragma unroll
        for (int u = 0; u < 4; u++) o[j][u] = 0.f;
    float l0 = 0.f, l1 = 0.f;

    const int grow0 = qb * 64 + arow;
    const int grow1 = grow0 + 8;

    for (int t = 0; t <= qb; t++) {
        if (t + 1 <= qb) load_kv(t + 1);
        if (t < qb) { CP_WAIT(1); } else { CP_WAIT(0); }
        __syncthreads();   // KV ready; also orders Q-hoist before first P write

        const uint32_t kbase = sbase + (FW_K + (t & 1) * 64 * QPH) * 4;
        const uint32_t vbase = sbase + (FW_V + (t & 1) * 64 * VPH) * 4;

        // ---- S = Q @ K^T ----
        float c[8][4];
#pragma unroll
        for (int j = 0; j < 8; j++)
#pragma unroll
            for (int u = 0; u < 4; u++) c[j][u] = 0.f;

#pragma unroll
        for (int ks = 0; ks < 4; ks++) {
            uint32_t b[8][2];
#pragma unroll
            for (int jp = 0; jp < 4; jp++)
                ldsm4(b[2*jp][0], b[2*jp][1], b[2*jp+1][0], b[2*jp+1][1],
                      kbase + koff_b + (jp * 16 * QPH + ks * 8) * 4);
#pragma unroll
            for (int j = 0; j < 8; j++)
                mma16(c[j], qf[ks], b[j]);
        }

        // ---- causal mask + exp (FMA pipe) + row sums ----
        const bool diag = (t == qb);
        float s0 = 0.f, s1 = 0.f;
#pragma unroll
        for (int j = 0; j < 8; j++) {
            int col = t * 64 + j * 8 + 2 * q4;
            if (diag) {
                if (col     > grow0) c[j][0] = -1e9f;
                if (col + 1 > grow0) c[j][1] = -1e9f;
                if (col     > grow1) c[j][2] = -1e9f;
                if (col + 1 > grow1) c[j][3] = -1e9f;
            }
            c[j][0] = fexp_s(c[j][0]);
            c[j][1] = fexp_s(c[j][1]);
            c[j][2] = fexp_s(c[j][2]);
            c[j][3] = fexp_s(c[j][3]);
            s0 += c[j][0] + c[j][1];
            s1 += c[j][2] + c[j][3];
        }
        s0 += __shfl_xor_sync(0xffffffffu, s0, 1);
        s0 += __shfl_xor_sync(0xffffffffu, s0, 2);
        s1 += __shfl_xor_sync(0xffffffffu, s1, 1);
        s1 += __shfl_xor_sync(0xffffffffu, s1, 2);
        l0 += s0;
        l1 += s1;

        // ---- P -> smem (per-warp rows; aliased Q buffer), then O += P @ V ----
        __syncwarp();
#pragma unroll
        for (int j = 0; j < 8; j++) {
            int pw = j * 4 + q4;
            QPs[arow * QPH + pw]       = pack_h2(c[j][0], c[j][1]);
            QPs[(arow + 8) * QPH + pw] = pack_h2(c[j][2], c[j][3]);
        }
        __syncwarp();

#pragma unroll
        for (int ks = 0; ks < 4; ks++) {
            uint32_t a[4], b[8][2];
            ldsm4(a[0], a[1], a[2], a[3],
                  sbase + poff_a + (ks * 8) * 4);
#pragma unroll
            for (int jp = 0; jp < 4; jp++)
                ldsm4t(b[2*jp][0], b[2*jp][1], b[2*jp+1][0], b[2*jp+1][1],
                       vbase + voff_b + (ks * 16 * VPH + jp * 8) * 4);
#pragma unroll
            for (int j = 0; j < 8; j++)
                mma16(o[j], a, b[j]);
        }
        __syncthreads();   // KV buffer reuse safety
    }

    // ---- normalize + store as half ----
    const float inv0 = 1.f / l0, inv1 = 1.f / l1;
    const int row0 = qb * 64 + arow;
#pragma unroll
    for (int j = 0; j < 8; j++) {
        int col = j * 8 + 2 * q4;
        __half* p0 = go + hbase + (size_t)row0 * DIMM + col;
        *(uint32_t*)p0              = pack_h2(o[j][0] * inv0, o[j][1] * inv0);
        *(uint32_t*)(p0 + 8 * DIMM) = pack_h2(o[j][2] * inv1, o[j][3] * inv1);
    }
}

// ===========================================================================
extern "C" void kernel_launch(void* const* d_in, const int* in_sizes, int n_in,
                              void* d_out, int out_size)
{
    (void)in_sizes; (void)n_in; (void)out_size;
    const float* x  = (const float*)d_in[0];
    const float* wq = (const float*)d_in[2];
    const float* wk = (const float*)d_in[3];
    const float* wv = (const float*)d_in[4];
    const float* wo = (const float*)d_in[5];
    float* out = (float*)d_out;

    __half *qh, *kh, *vh, *att, *xh, *wh;
    cudaGetSymbolAddress((void**)&qh,  g_qh);
    cudaGetSymbolAddress((void**)&kh,  g_kh);
    cudaGetSymbolAddress((void**)&vh,  g_vh);
    cudaGetSymbolAddress((void**)&att, g_att);
    cudaGetSymbolAddress((void**)&xh,  g_xh);
    cudaGetSymbolAddress((void**)&wh,  g_wh);

    cudaFuncSetAttribute(gemm_h<true>,  cudaFuncAttributeMaxDynamicSharedMemorySize, GSMEM_BYTES);
    cudaFuncSetAttribute(gemm_h<false>, cudaFuncAttributeMaxDynamicSharedMemorySize, GSMEM_BYTES);
    cudaFuncSetAttribute(flash_h,       cudaFuncAttributeMaxDynamicSharedMemorySize, FSMEM_BYTES);

    const int xn4 = MROWS * DIMM / 4;
    const int wn4 = WFLOATS / 4;
    round_h<<<xn4 / 256, 256>>>(x, xh, xn4);
    round_h4<<<dim3(wn4 / 256, 4), 256>>>(wq, wk, wv, wo, wh, wn4);

    gemm_h<true><<<dim3(DIMM / 128, MROWS / 128, 3), 256, GSMEM_BYTES>>>(
        xh, wh + 0 * WFLOATS, wh + 1 * WFLOATS, wh + 2 * WFLOATS, qh, kh, vh);

    flash_h<<<dim3(SEQ / 64, BATCH * NHEADS), 128, FSMEM_BYTES>>>(qh, kh, vh, att);

    gemm_h<false><<<dim3(DIMM / 128, MROWS / 128, 1), 256, GSMEM_BYTES>>>(
        att, wh + 3 * WFLOATS, wh + 3 * WFLOATS, wh + 3 * WFLOATS, out, out, out);
}